// round 5
// baseline (speedup 1.0000x reference)
#include <cuda_runtime.h>
#include <math.h>

#define D 256
#define H 128
#define BN 24            // nodes per block (12 packed pairs)
#define NP (BN/2)        // node pairs
#define GAMMA   (-0.5f)
#define ZETA    (1.1f)
#define DBGVAR  (1e-7f)

// scratch (allocation-free rule: __device__ globals)
__device__ float g_snb[65536];
__device__ float g_sself[65536];
__device__ float g_rowsum[65536];
__device__ float g_mv[1 << 20];

// ---- packed f32x2 helpers (Blackwell FFMA2) --------------------------------
__device__ __forceinline__ void ffma2(unsigned long long& acc,
                                      unsigned long long a,
                                      unsigned long long b) {
    asm("fma.rn.f32x2 %0, %1, %2, %0;" : "+l"(acc) : "l"(a), "l"(b));
}
__device__ __forceinline__ unsigned long long pack2(float lo, float hi) {
    unsigned long long r;
    asm("mov.b64 %0, {%1, %2};" : "=l"(r) : "f"(lo), "f"(hi));
    return r;
}
__device__ __forceinline__ void unpack2(unsigned long long v, float& lo, float& hi) {
    asm("mov.b64 {%0, %1}, %2;" : "=f"(lo), "=f"(hi) : "l"(v));
}

// ---------------------------------------------------------------------------
// Kernel 1: per-node attention scores + rowsum zero-init
//   s_nb[n]   = relu(x[n] @ W_nb   + b_nb)   . W_att[0:H]
//   s_self[n] = relu(x[n] @ W_self + b_self) . W_att[H:2H]
// 128 threads = one h-column each; BN=24 nodes per block, packed in pairs so
// every fma.rn.f32x2 does 2 node-FMAs.
// ---------------------------------------------------------------------------
__global__ __launch_bounds__(128)
void node_scores_kernel(const float* __restrict__ x,
                        const float* __restrict__ Wnb,
                        const float* __restrict__ bnb,
                        const float* __restrict__ Wself,
                        const float* __restrict__ bself,
                        const float* __restrict__ Watt,
                        int N)
{
    __shared__ float xsT[D * BN];           // transposed tile: [d][node], 24 KB
    __shared__ float red_nb[4][BN];
    __shared__ float red_self[4][BN];

    const int t     = threadIdx.x;          // 0..127 (h index)
    const int warp  = t >> 5;
    const int lane  = t & 31;
    const int node0 = blockIdx.x * BN;

    // zero rowsum (grid * 128 threads comfortably covers N)
    int gid = blockIdx.x * blockDim.x + t;
    if (gid < N) g_rowsum[gid] = 0.0f;

    // load x tile into smem, transposed (coalesced global reads)
    for (int i = t; i < BN * D; i += 128) {
        int j = i >> 8;          // i / D
        int d = i & (D - 1);     // i % D
        int n = node0 + j;
        xsT[d * BN + j] = (n < N) ? x[n * D + d] : 0.0f;
    }
    __syncthreads();

    unsigned long long accn[NP], accs[NP];
#pragma unroll
    for (int p = 0; p < NP; p++) { accn[p] = 0ull; accs[p] = 0ull; }

    const unsigned long long* xs64 =
        reinterpret_cast<const unsigned long long*>(xsT);

    for (int d0 = 0; d0 < D; d0 += 4) {
        float wn[4], ws[4];
#pragma unroll
        for (int k = 0; k < 4; k++) {
            wn[k] = Wnb[(d0 + k) * H + t];
            ws[k] = Wself[(d0 + k) * H + t];
        }
#pragma unroll
        for (int k = 0; k < 4; k++) {
            unsigned long long wn2 = pack2(wn[k], wn[k]);
            unsigned long long ws2 = pack2(ws[k], ws[k]);
            int base = (d0 + k) * NP;       // pair index base for this d
#pragma unroll
            for (int q = 0; q < NP / 2; q++) {
                ulonglong2 xv = *reinterpret_cast<const ulonglong2*>(
                    &xs64[base + 2 * q]);   // 16B aligned: base*8 % 16 == 0
                ffma2(accn[2 * q],     xv.x, wn2);
                ffma2(accn[2 * q + 1], xv.y, wn2);
                ffma2(accs[2 * q],     xv.x, ws2);
                ffma2(accs[2 * q + 1], xv.y, ws2);
            }
        }
    }

    // epilogue: relu, weight by w_att, reduce over the 128 h-columns
    const float bn = bnb[t];
    const float bs = bself[t];
    const float w1 = Watt[t];
    const float w2 = Watt[H + t];

#pragma unroll
    for (int p = 0; p < NP; p++) {
        float a0, a1, s0, s1;
        unpack2(accn[p], a0, a1);
        unpack2(accs[p], s0, s1);
#pragma unroll
        for (int half = 0; half < 2; half++) {
            float va = half ? a1 : a0;
            float vs = half ? s1 : s0;
            float v1 = fmaxf(va + bn, 0.0f) * w1;
            float v2 = fmaxf(vs + bs, 0.0f) * w2;
#pragma unroll
            for (int off = 16; off > 0; off >>= 1) {
                v1 += __shfl_down_sync(0xffffffff, v1, off);
                v2 += __shfl_down_sync(0xffffffff, v2, off);
            }
            if (lane == 0) {
                red_nb[warp][2 * p + half]   = v1;
                red_self[warp][2 * p + half] = v2;
            }
        }
    }
    __syncthreads();

    if (t < BN && node0 + t < N) {
        float s1 = red_nb[0][t] + red_nb[1][t] + red_nb[2][t] + red_nb[3][t];
        float s2 = red_self[0][t] + red_self[1][t] + red_self[2][t] + red_self[3][t];
        g_snb[node0 + t]   = s1;
        g_sself[node0 + t] = s2;
    }
}

// ---------------------------------------------------------------------------
// Kernel 2: per-edge mask + masked value + rowsum scatter
// ---------------------------------------------------------------------------
__global__ __launch_bounds__(256)
void edge_mask_kernel(const float* __restrict__ values,
                      const float* __restrict__ noise,
                      const int*   __restrict__ row,
                      const int*   __restrict__ col,
                      const float* __restrict__ batt,
                      int E)
{
    int e = blockIdx.x * blockDim.x + threadIdx.x;
    if (e >= E) return;

    const float ba = __ldg(batt);

    int r = row[e];
    int c = col[e];
    float la = g_snb[r] + g_sself[c] + ba;

    float u = noise[e] + DBGVAR;
    float z = logf(u) - logf(1.0f - u) + la;
    float gate = 1.0f / (1.0f + expf(-z));
    float mask = fminf(fmaxf(gate * (ZETA - GAMMA) + GAMMA, 0.0f), 1.0f);
    float mv = values[e] * mask;

    g_mv[e] = mv;
    if (mv != 0.0f) atomicAdd(&g_rowsum[r], mv);
}

// ---------------------------------------------------------------------------
// Kernel 3: degree normalization
// ---------------------------------------------------------------------------
__global__ __launch_bounds__(256)
void edge_norm_kernel(const int* __restrict__ row,
                      const int* __restrict__ col,
                      float* __restrict__ out,
                      int E)
{
    int e = blockIdx.x * blockDim.x + threadIdx.x;
    if (e >= E) return;

    float mv = g_mv[e];
    float dr = 1.0f / sqrtf(g_rowsum[row[e]] + 1e-10f);
    float dc = 1.0f / sqrtf(g_rowsum[col[e]] + 1e-10f);
    out[e] = mv * dr * dc;
}

// ---------------------------------------------------------------------------
extern "C" void kernel_launch(void* const* d_in, const int* in_sizes, int n_in,
                              void* d_out, int out_size)
{
    const float* x      = (const float*)d_in[0];
    const float* Wnb    = (const float*)d_in[1];
    const float* bnb    = (const float*)d_in[2];
    const float* Wself  = (const float*)d_in[3];
    const float* bself  = (const float*)d_in[4];
    const float* Watt   = (const float*)d_in[5];
    const float* batt   = (const float*)d_in[6];
    const float* values = (const float*)d_in[7];
    const float* noise  = (const float*)d_in[8];
    const int*   row    = (const int*)d_in[9];
    const int*   col    = (const int*)d_in[10];
    float* out = (float*)d_out;

    int N = in_sizes[0] / D;     // 50000
    int E = in_sizes[7];         // 800000

    int nodeBlocks = (N + BN - 1) / BN;
    node_scores_kernel<<<nodeBlocks, 128>>>(x, Wnb, bnb, Wself, bself, Watt, N);

    int edgeBlocks = (E + 255) / 256;
    edge_mask_kernel<<<edgeBlocks, 256>>>(values, noise, row, col, batt, E);
    edge_norm_kernel<<<edgeBlocks, 256>>>(row, col, out, E);
}

// round 6
// speedup vs baseline: 1.0013x; 1.0013x over previous
#include <cuda_runtime.h>
#include <math.h>

#define D 256
#define H 128
#define BN 16            // nodes per block (8 packed pairs)
#define NP (BN/2)        // node pairs
#define GAMMA   (-0.5f)
#define ZETA    (1.1f)
#define DBGVAR  (1e-7f)

// scratch (allocation-free rule: __device__ globals)
__device__ float g_snb[65536];
__device__ float g_sself[65536];
__device__ float g_rowsum[65536];
__device__ float g_mv[1 << 20];

// ---- packed f32x2 helpers (Blackwell FFMA2) --------------------------------
__device__ __forceinline__ void ffma2(unsigned long long& acc,
                                      unsigned long long a,
                                      unsigned long long b) {
    asm("fma.rn.f32x2 %0, %1, %2, %0;" : "+l"(acc) : "l"(a), "l"(b));
}
__device__ __forceinline__ unsigned long long pack2(float lo, float hi) {
    unsigned long long r;
    asm("mov.b64 %0, {%1, %2};" : "=l"(r) : "f"(lo), "f"(hi));
    return r;
}
__device__ __forceinline__ void unpack2(unsigned long long v, float& lo, float& hi) {
    asm("mov.b64 {%0, %1}, %2;" : "=f"(lo), "=f"(hi) : "l"(v));
}

// ---------------------------------------------------------------------------
// Kernel 1: per-node attention scores + rowsum zero-init
//   s_nb[n]   = relu(x[n] @ W_nb   + b_nb)   . W_att[0:H]
//   s_self[n] = relu(x[n] @ W_self + b_self) . W_att[H:2H]
// 128 threads = one h-column each; BN=16 nodes packed in 8 f32x2 pairs.
// W loads are software-pipelined (register double buffer) to hide L2 latency.
// ---------------------------------------------------------------------------
__global__ __launch_bounds__(128)
void node_scores_kernel(const float* __restrict__ x,
                        const float* __restrict__ Wnb,
                        const float* __restrict__ bnb,
                        const float* __restrict__ Wself,
                        const float* __restrict__ bself,
                        const float* __restrict__ Watt,
                        int N)
{
    __shared__ float xsT[D * BN];           // transposed tile: [d][node], 16 KB
    __shared__ float red_nb[4][BN];
    __shared__ float red_self[4][BN];

    const int t     = threadIdx.x;          // 0..127 (h index)
    const int warp  = t >> 5;
    const int lane  = t & 31;
    const int node0 = blockIdx.x * BN;

    // zero rowsum (3125 blocks * 128 threads = 400K >= N)
    int gid = blockIdx.x * blockDim.x + t;
    if (gid < N) g_rowsum[gid] = 0.0f;

    // load x tile into smem, transposed (coalesced global reads)
    for (int i = t; i < BN * D; i += 128) {
        int j = i >> 8;          // i / D
        int d = i & (D - 1);     // i % D
        int n = node0 + j;
        xsT[d * BN + j] = (n < N) ? x[n * D + d] : 0.0f;
    }
    __syncthreads();

    unsigned long long accn[NP], accs[NP];
#pragma unroll
    for (int p = 0; p < NP; p++) { accn[p] = 0ull; accs[p] = 0ull; }

    const unsigned long long* xs64 =
        reinterpret_cast<const unsigned long long*>(xsT);

    // register double-buffer for W chunk (8 floats / matrix / chunk)
    float wnc[4], wsc[4];
#pragma unroll
    for (int k = 0; k < 4; k++) {
        wnc[k] = Wnb[k * H + t];
        wsc[k] = Wself[k * H + t];
    }

    for (int d0 = 0; d0 < D; d0 += 4) {
        // prefetch next chunk's W (wraps to 0 on last iter; harmless)
        int dn = (d0 + 4 < D) ? (d0 + 4) : 0;
        float wnn[4], wsn[4];
#pragma unroll
        for (int k = 0; k < 4; k++) {
            wnn[k] = Wnb[(dn + k) * H + t];
            wsn[k] = Wself[(dn + k) * H + t];
        }

#pragma unroll
        for (int k = 0; k < 4; k++) {
            unsigned long long wn2 = pack2(wnc[k], wnc[k]);
            unsigned long long ws2 = pack2(wsc[k], wsc[k]);
            int base = (d0 + k) * NP;       // pair index base for this d
#pragma unroll
            for (int q = 0; q < NP / 2; q++) {
                ulonglong2 xv = *reinterpret_cast<const ulonglong2*>(
                    &xs64[base + 2 * q]);   // 16B aligned (NP even)
                ffma2(accn[2 * q],     xv.x, wn2);
                ffma2(accn[2 * q + 1], xv.y, wn2);
                ffma2(accs[2 * q],     xv.x, ws2);
                ffma2(accs[2 * q + 1], xv.y, ws2);
            }
        }

#pragma unroll
        for (int k = 0; k < 4; k++) { wnc[k] = wnn[k]; wsc[k] = wsn[k]; }
    }

    // epilogue: relu, weight by w_att, reduce over the 128 h-columns
    const float bn = bnb[t];
    const float bs = bself[t];
    const float w1 = Watt[t];
    const float w2 = Watt[H + t];

#pragma unroll
    for (int p = 0; p < NP; p++) {
        float a0, a1, s0, s1;
        unpack2(accn[p], a0, a1);
        unpack2(accs[p], s0, s1);
#pragma unroll
        for (int half = 0; half < 2; half++) {
            float va = half ? a1 : a0;
            float vs = half ? s1 : s0;
            float v1 = fmaxf(va + bn, 0.0f) * w1;
            float v2 = fmaxf(vs + bs, 0.0f) * w2;
#pragma unroll
            for (int off = 16; off > 0; off >>= 1) {
                v1 += __shfl_down_sync(0xffffffff, v1, off);
                v2 += __shfl_down_sync(0xffffffff, v2, off);
            }
            if (lane == 0) {
                red_nb[warp][2 * p + half]   = v1;
                red_self[warp][2 * p + half] = v2;
            }
        }
    }
    __syncthreads();

    if (t < BN && node0 + t < N) {
        float s1 = red_nb[0][t] + red_nb[1][t] + red_nb[2][t] + red_nb[3][t];
        float s2 = red_self[0][t] + red_self[1][t] + red_self[2][t] + red_self[3][t];
        g_snb[node0 + t]   = s1;
        g_sself[node0 + t] = s2;
    }
}

// ---------------------------------------------------------------------------
// Kernel 2: per-edge mask + masked value + rowsum scatter
// ---------------------------------------------------------------------------
__global__ __launch_bounds__(256)
void edge_mask_kernel(const float* __restrict__ values,
                      const float* __restrict__ noise,
                      const int*   __restrict__ row,
                      const int*   __restrict__ col,
                      const float* __restrict__ batt,
                      int E)
{
    int e = blockIdx.x * blockDim.x + threadIdx.x;
    if (e >= E) return;

    const float ba = __ldg(batt);

    int r = row[e];
    int c = col[e];
    float la = g_snb[r] + g_sself[c] + ba;

    float u = noise[e] + DBGVAR;
    float z = logf(u) - logf(1.0f - u) + la;
    float gate = 1.0f / (1.0f + expf(-z));
    float mask = fminf(fmaxf(gate * (ZETA - GAMMA) + GAMMA, 0.0f), 1.0f);
    float mv = values[e] * mask;

    g_mv[e] = mv;
    if (mv != 0.0f) atomicAdd(&g_rowsum[r], mv);
}

// ---------------------------------------------------------------------------
// Kernel 3: degree normalization
// ---------------------------------------------------------------------------
__global__ __launch_bounds__(256)
void edge_norm_kernel(const int* __restrict__ row,
                      const int* __restrict__ col,
                      float* __restrict__ out,
                      int E)
{
    int e = blockIdx.x * blockDim.x + threadIdx.x;
    if (e >= E) return;

    float mv = g_mv[e];
    float dr = 1.0f / sqrtf(g_rowsum[row[e]] + 1e-10f);
    float dc = 1.0f / sqrtf(g_rowsum[col[e]] + 1e-10f);
    out[e] = mv * dr * dc;
}

// ---------------------------------------------------------------------------
extern "C" void kernel_launch(void* const* d_in, const int* in_sizes, int n_in,
                              void* d_out, int out_size)
{
    const float* x      = (const float*)d_in[0];
    const float* Wnb    = (const float*)d_in[1];
    const float* bnb    = (const float*)d_in[2];
    const float* Wself  = (const float*)d_in[3];
    const float* bself  = (const float*)d_in[4];
    const float* Watt   = (const float*)d_in[5];
    const float* batt   = (const float*)d_in[6];
    const float* values = (const float*)d_in[7];
    const float* noise  = (const float*)d_in[8];
    const int*   row    = (const int*)d_in[9];
    const int*   col    = (const int*)d_in[10];
    float* out = (float*)d_out;

    int N = in_sizes[0] / D;     // 50000
    int E = in_sizes[7];         // 800000

    int nodeBlocks = (N + BN - 1) / BN;
    node_scores_kernel<<<nodeBlocks, 128>>>(x, Wnb, bnb, Wself, bself, Watt, N);

    int edgeBlocks = (E + 255) / 256;
    edge_mask_kernel<<<edgeBlocks, 256>>>(values, noise, row, col, batt, E);
    edge_norm_kernel<<<edgeBlocks, 256>>>(row, col, out, E);
}